// round 5
// baseline (speedup 1.0000x reference)
#include <cuda_runtime.h>
#include <cuda_bf16.h>
#include <math.h>
#include <stdint.h>

#define N 1024
#define BATCH 32
#define NMAT 33          // 32 batch Laplacians + L0
#define EPSF 1e-7f
#define NSINK 40

// ---------------- static device scratch ------------------------------------
static __device__ float g_V[N * 4];
static __device__ float g_Ws[(size_t)N * N];
static __device__ float g_PrInv[BATCH * N];
static __device__ float g_col0[BATCH * N];
static __device__ float g_LU[(size_t)NMAT * N * N];
static __device__ float g_invd[NMAT * 64];
static __device__ float g_y[BATCH];
static __device__ float g_ld[NMAT];
// bf16 split scratch (A: [abs row][64] k-contig; B: [abs col][64] k-contig)
static __device__ __nv_bfloat16 g_Ahi[(size_t)NMAT * N * 64];
static __device__ __nv_bfloat16 g_Alo[(size_t)NMAT * N * 64];
static __device__ __nv_bfloat16 g_Bhi[(size_t)NMAT * N * 64];
static __device__ __nv_bfloat16 g_Blo[(size_t)NMAT * N * 64];

// ---------------- warp-mma helpers (generic PTX, sm_80+) --------------------
__device__ __forceinline__ uint32_t smem_to_u32(const void* p) {
    uint32_t a;
    asm("{ .reg .u64 t; cvta.to.shared.u64 t, %1; cvt.u32.u64 %0, t; }"
        : "=r"(a) : "l"(p));
    return a;
}
__device__ __forceinline__ void ldsm_x4(uint32_t* r, uint32_t addr) {
    asm volatile("ldmatrix.sync.aligned.m8n8.x4.shared.b16 {%0,%1,%2,%3}, [%4];"
        : "=r"(r[0]), "=r"(r[1]), "=r"(r[2]), "=r"(r[3]) : "r"(addr));
}
__device__ __forceinline__ void mma16816(float* d, const uint32_t* a, const uint32_t* b) {
    asm volatile(
        "mma.sync.aligned.m16n8k16.row.col.f32.bf16.bf16.f32 "
        "{%0,%1,%2,%3}, {%4,%5,%6,%7}, {%8,%9}, {%0,%1,%2,%3};"
        : "+f"(d[0]), "+f"(d[1]), "+f"(d[2]), "+f"(d[3])
        : "r"(a[0]), "r"(a[1]), "r"(a[2]), "r"(a[3]), "r"(b[0]), "r"(b[1]));
}

// ---------------- prep kernels ----------------------------------------------

__global__ void k_vsoftmax(const float* __restrict__ Vc) {
    int i = blockIdx.x * 256 + threadIdx.x;
    if (i >= N) return;
    float4 v = reinterpret_cast<const float4*>(Vc)[i];
    float m = fmaxf(fmaxf(v.x, v.y), fmaxf(v.z, v.w));
    float a = __expf(v.x - m), b = __expf(v.y - m), c = __expf(v.z - m), d = __expf(v.w - m);
    float r = 1.0f / (a + b + c + d);
    float4 o; o.x = a * r; o.y = b * r; o.z = c * r; o.w = d * r;
    reinterpret_cast<float4*>(g_V)[i] = o;
}

__global__ void k_pr(const int* __restrict__ x) {
    int b = blockIdx.x;
    int i = threadIdx.x;
    int xi = x[b * N + i];
    float pr = g_V[i * 4 + xi];
    g_PrInv[b * N + i] = 1.0f / pr;
    __shared__ float sm[N];
    sm[i] = logf(pr + 1e-7f);
    __syncthreads();
    for (int st = 512; st > 0; st >>= 1) {
        if (i < st) sm[i] += sm[i + st];
        __syncthreads();
    }
    if (i == 0) g_y[b] = sm[0];
}

__global__ void k_ws(const float* __restrict__ W) {
    int i = blockIdx.x;
    __shared__ float sWs[N];
    __shared__ float sm[256];
    float s = 0.0f;
    for (int j = threadIdx.x; j < N; j += 256) {
        float v;
        if (i == j) v = 0.0f;
        else {
            float w = (i > j) ? W[(size_t)i * N + j] : W[(size_t)j * N + i];
            v = 1.0f / (1.0f + __expf(-w));
        }
        g_Ws[(size_t)i * N + j] = v;
        sWs[j] = v;
        s += v;
    }
    sm[threadIdx.x] = s;
    __syncthreads();
    for (int st = 128; st > 0; st >>= 1) {
        if (threadIdx.x < st) sm[threadIdx.x] += sm[threadIdx.x + st];
        __syncthreads();
    }
    float rowsum = sm[0];
    float* L0 = g_LU + (size_t)32 * N * N;
    if (i >= 1) {
        int p = i - 1;
        for (int q = threadIdx.x; q < N; q += 256) {
            float v;
            if (q == 1023) v = 0.0f;
            else v = ((q == p) ? rowsum : 0.0f) - sWs[q + 1] + 1e-7f;
            L0[(size_t)p * N + q] = v;
        }
    } else {
        for (int q = threadIdx.x; q < N; q += 256)
            L0[(size_t)1023 * N + q] = (q == 1023) ? 1.0f : 0.0f;
    }
}

// ---------------- Sinkhorn + scatter ----------------------------------------
__global__ void k_sink(const int* __restrict__ x, const float* __restrict__ Ec) {
    int tid = threadIdx.x;
    int j = blockIdx.x * 128 + tid;
    int i = blockIdx.y + 1;

    __shared__ float se[128 * 17];
    __shared__ int   sxi[BATCH];
    __shared__ float spi[BATCH];
    if (tid < BATCH) {
        sxi[tid] = x[tid * N + i];
        spi[tid] = g_PrInv[tid * N + i];
    }

    float e[16];
    if (i != j) {
        const float4* p = reinterpret_cast<const float4*>(Ec) + (size_t)(i * N + j) * 4;
        float4 q0 = p[0], q1 = p[1], q2 = p[2], q3 = p[3];
        e[0] = __expf(q0.x); e[1] = __expf(q0.y); e[2] = __expf(q0.z); e[3] = __expf(q0.w);
        e[4] = __expf(q1.x); e[5] = __expf(q1.y); e[6] = __expf(q1.z); e[7] = __expf(q1.w);
        e[8] = __expf(q2.x); e[9] = __expf(q2.y); e[10] = __expf(q2.z); e[11] = __expf(q2.w);
        e[12] = __expf(q3.x); e[13] = __expf(q3.y); e[14] = __expf(q3.z); e[15] = __expf(q3.w);
        float s = 0.0f;
        #pragma unroll
        for (int t = 0; t < 16; t++) s += e[t];
        float r0 = __fdividef(1.0f, s);
        #pragma unroll
        for (int t = 0; t < 16; t++) e[t] *= r0;

        float4 vi4 = reinterpret_cast<const float4*>(g_V)[i];
        float4 vj4 = reinterpret_cast<const float4*>(g_V)[j];
        float Vi[4] = {vi4.x, vi4.y, vi4.z, vi4.w};
        float Vj[4] = {vj4.x, vj4.y, vj4.z, vj4.w};

        #pragma unroll 1
        for (int it = 0; it < NSINK; ++it) {
            #pragma unroll
            for (int a = 0; a < 4; a++) {
                float rs = e[4*a] + e[4*a+1] + e[4*a+2] + e[4*a+3];
                float rr = __fdividef(Vi[a], rs + EPSF);
                e[4*a] *= rr; e[4*a+1] *= rr; e[4*a+2] *= rr; e[4*a+3] *= rr;
            }
            #pragma unroll
            for (int b = 0; b < 4; b++) {
                float cs = e[b] + e[b+4] + e[b+8] + e[b+12];
                float cc = __fdividef(Vj[b], cs + EPSF);
                e[b] *= cc; e[b+4] *= cc; e[b+8] *= cc; e[b+12] *= cc;
            }
        }
        float t = 0.0f;
        #pragma unroll
        for (int u = 0; u < 16; u++) t += e[u];
        float tr = __fdividef(1.0f, t + EPSF);
        #pragma unroll
        for (int u = 0; u < 16; u++)
            e[u] = fminf(fmaxf(e[u] * tr, 0.0f), 1.0f);
    } else {
        #pragma unroll
        for (int t = 0; t < 16; t++) e[t] = 0.0f;
    }

    #pragma unroll
    for (int t = 0; t < 16; t++) se[tid * 17 + t] = e[t];
    __syncthreads();

    float wij = g_Ws[(size_t)i * N + j];
    #pragma unroll 1
    for (int b = 0; b < BATCH; b++) {
        int a = sxi[b];
        int c = x[b * N + j];
        float val = wij * se[tid * 17 + (a * 4 + c)] * spi[b] * g_PrInv[b * N + j];
        if (j == 0) g_col0[b * N + i] = val;
        else g_LU[(size_t)b * N * N + (size_t)(i - 1) * N + (j - 1)] = 1e-7f - val;
    }
}

__global__ void k_fin() {
    int b = blockIdx.y;
    int p = blockIdx.x;
    float* row = g_LU + (size_t)b * N * N + (size_t)p * N;
    if (p == 1023) {
        for (int q = threadIdx.x; q < N; q += 256) row[q] = (q == 1023) ? 1.0f : 0.0f;
        return;
    }
    __shared__ float sm[256];
    float s = 0.0f;
    for (int q = threadIdx.x; q < 1023; q += 256) s += row[q];
    sm[threadIdx.x] = s;
    __syncthreads();
    for (int st = 128; st > 0; st >>= 1) {
        if (threadIdx.x < st) sm[threadIdx.x] += sm[threadIdx.x + st];
        __syncthreads();
    }
    if (threadIdx.x == 0) {
        float wpsum = 1023.0f * 1e-7f - sm[0] + g_col0[b * N + (p + 1)];
        row[p] = wpsum + 1e-7f;
        row[1023] = 0.0f;
    }
}

// ---------------- blocked unpivoted LU (nb = 64) ----------------------------

__global__ void k_panelLU(int k) {
    int mat = blockIdx.x;
    float* A = g_LU + (size_t)mat * N * N;
    __shared__ float sA[64][65];
    int tid = threadIdx.x;
    int cc = tid & 63;
    int rg = tid >> 6;
    for (int t = tid; t < 64 * 64; t += 256) {
        int r = t >> 6, c = t & 63;
        sA[r][c] = A[(size_t)(k + r) * N + k + c];
    }
    __syncthreads();
    #pragma unroll 1
    for (int c = 0; c < 64; c++) {
        if (tid >= c && tid < 64) {
            float inv = 1.0f / sA[c][c];
            if (tid == c) g_invd[mat * 64 + c] = inv;
            else sA[tid][c] *= inv;
        }
        __syncthreads();
        if (cc > c) {
            float ucc = sA[c][cc];
            #pragma unroll 1
            for (int r = c + 1 + rg; r < 64; r += 4)
                sA[r][cc] -= sA[r][c] * ucc;
        }
        __syncthreads();
    }
    for (int t = tid; t < 64 * 64; t += 256) {
        int r = t >> 6, c = t & 63;
        A[(size_t)(k + r) * N + k + c] = sA[r][c];
    }
}

__global__ void k_trsm(int k) {
    int mat = blockIdx.y;
    float* A = g_LU + (size_t)mat * N * N;
    int tid = threadIdx.x;
    __shared__ float sU[64][65];
    __shared__ float sInv[64];
    for (int t = tid; t < 64 * 64; t += 256) {
        int r = t >> 6, c = t & 63;
        sU[r][c] = A[(size_t)(k + r) * N + k + c];
    }
    if (blockIdx.z == 0 && tid < 64) sInv[tid] = g_invd[mat * 64 + tid];
    __syncthreads();
    int g = k + 64 + blockIdx.x * 256 + tid;
    if (g >= N) return;
    if (blockIdx.z == 0) {
        float* rowp = A + (size_t)g * N + k;
        float a[64];
        #pragma unroll
        for (int c = 0; c < 16; c++) {
            float4 v = reinterpret_cast<const float4*>(rowp)[c];
            a[4 * c] = v.x; a[4 * c + 1] = v.y; a[4 * c + 2] = v.z; a[4 * c + 3] = v.w;
        }
        #pragma unroll
        for (int d = 0; d < 64; d++) {
            a[d] *= sInv[d];
            #pragma unroll
            for (int c = d + 1; c < 64; c++) a[c] -= a[d] * sU[d][c];
        }
        #pragma unroll
        for (int c = 0; c < 16; c++) {
            float4 v; v.x = a[4 * c]; v.y = a[4 * c + 1]; v.z = a[4 * c + 2]; v.w = a[4 * c + 3];
            reinterpret_cast<float4*>(rowp)[c] = v;
        }
    } else {
        float a[64];
        #pragma unroll
        for (int d = 0; d < 64; d++) a[d] = A[(size_t)(k + d) * N + g];
        #pragma unroll
        for (int d = 0; d < 64; d++) {
            #pragma unroll
            for (int r = d + 1; r < 64; r++) a[r] -= sU[r][d] * a[d];
        }
        #pragma unroll
        for (int d = 0; d < 64; d++) A[(size_t)(k + d) * N + g] = a[d];
    }
}

// split L21 / U12 into bf16 hi/lo scratch (B transposed to [col][k] K-major)
__global__ void k_conv(int k) {
    int mat = blockIdx.y;
    const float* M = g_LU + (size_t)mat * N * N;
    int t = threadIdx.x;
    size_t mo = (size_t)mat * N * 64;
    if (blockIdx.z == 0) {
        int row0 = k + 64 + blockIdx.x * 64;
        #pragma unroll 4
        for (int it = 0; it < 16; it++) {
            int idx = it * 256 + t;
            int r = row0 + (idx >> 6), d = idx & 63;
            float v = M[(size_t)r * N + k + d];
            __nv_bfloat16 h = __float2bfloat16(v);
            __nv_bfloat16 l = __float2bfloat16(v - __bfloat162float(h));
            g_Ahi[mo + (size_t)r * 64 + d] = h;
            g_Alo[mo + (size_t)r * 64 + d] = l;
        }
    } else {
        __shared__ float s[64][65];
        int c0 = k + 64 + blockIdx.x * 64;
        #pragma unroll 4
        for (int it = 0; it < 16; it++) {
            int idx = it * 256 + t;
            int d = idx >> 6, c = idx & 63;
            s[d][c] = M[(size_t)(k + d) * N + c0 + c];
        }
        __syncthreads();
        #pragma unroll 4
        for (int it = 0; it < 16; it++) {
            int idx = it * 256 + t;
            int c = idx >> 6, d = idx & 63;
            float v = s[d][c];
            __nv_bfloat16 h = __float2bfloat16(v);
            __nv_bfloat16 l = __float2bfloat16(v - __bfloat162float(h));
            g_Bhi[mo + (size_t)(c0 + c) * 64 + d] = h;
            g_Blo[mo + (size_t)(c0 + c) * 64 + d] = l;
        }
    }
}

// ---------------- HMMA trailing update: C -= L21*U12 ------------------------
// 128x128 C tile, 256 threads (8 warps as 4x2), 3-term bf16 split, fp32 acc.
// smem rows padded to 72 bf16 (144B) -> conflict-free ldmatrix.
#define SROW 72
#define SM_A_HI 0
#define SM_A_LO (128 * SROW * 2)
#define SM_B_HI (2 * 128 * SROW * 2)
#define SM_B_LO (3 * 128 * SROW * 2)
#define SM_MMA_BYTES (4 * 128 * SROW * 2)

__global__ void __launch_bounds__(256) k_gemm_mma(int k) {
    extern __shared__ __align__(16) char smc[];
    uint32_t sb = smem_to_u32(smc);
    int mat = blockIdx.z;
    float* M = g_LU + (size_t)mat * N * N;
    size_t mo = (size_t)mat * N * 64;
    int row0 = k + 64 + blockIdx.y * 128;
    int col0 = k + 64 + blockIdx.x * 128;
    int tid = threadIdx.x;
    int lane = tid & 31, wid = tid >> 5;

    // ---- load 4 arrays (128 rows x 64 bf16) into padded smem ----
    {
        int r = tid >> 1;
        int h = (tid & 1) * 4;
        int ga = min(row0 + r, N - 1);
        int gb = min(col0 + r, N - 1);
        const uint4* pAhi = reinterpret_cast<const uint4*>(g_Ahi + mo + (size_t)ga * 64);
        const uint4* pAlo = reinterpret_cast<const uint4*>(g_Alo + mo + (size_t)ga * 64);
        const uint4* pBhi = reinterpret_cast<const uint4*>(g_Bhi + mo + (size_t)gb * 64);
        const uint4* pBlo = reinterpret_cast<const uint4*>(g_Blo + mo + (size_t)gb * 64);
        #pragma unroll
        for (int c = 0; c < 4; c++) {
            int chunk = h + c;
            size_t so = (size_t)r * SROW * 2 + chunk * 16;
            *reinterpret_cast<uint4*>(smc + SM_A_HI + so) = pAhi[chunk];
            *reinterpret_cast<uint4*>(smc + SM_A_LO + so) = pAlo[chunk];
            *reinterpret_cast<uint4*>(smc + SM_B_HI + so) = pBhi[chunk];
            *reinterpret_cast<uint4*>(smc + SM_B_LO + so) = pBlo[chunk];
        }
    }
    __syncthreads();

    int wm = (wid & 3) * 32;        // warp row offset in tile
    int wn = (wid >> 2) * 64;       // warp col offset in tile

    float acc[2][8][4];
    #pragma unroll
    for (int mi = 0; mi < 2; mi++)
        #pragma unroll
        for (int ni = 0; ni < 8; ni++)
            #pragma unroll
            for (int q = 0; q < 4; q++) acc[mi][ni][q] = 0.0f;

    // lane-dependent ldmatrix base addresses (bytes)
    uint32_t aBase = sb + SM_A_HI +
        (uint32_t)(((wm + (lane & 15)) * SROW + (lane >> 4) * 8) * 2);
    uint32_t bBase = sb + SM_B_HI +
        (uint32_t)(((wn + (lane >> 4) * 8 + (lane & 7)) * SROW + ((lane >> 3) & 1) * 8) * 2);
    const uint32_t LO = (uint32_t)(128 * SROW * 2);

    #pragma unroll
    for (int ks = 0; ks < 4; ks++) {
        uint32_t ko = ks * 16 * 2;   // k0*2 bytes
        uint32_t a_hi[2][4], a_lo[2][4];
        uint32_t b_hi[4][4], b_lo[4][4];
        #pragma unroll
        for (int mi = 0; mi < 2; mi++) {
            uint32_t ad = aBase + (uint32_t)(mi * 16 * SROW * 2) + ko;
            ldsm_x4(a_hi[mi], ad);
            ldsm_x4(a_lo[mi], ad + LO);
        }
        #pragma unroll
        for (int np = 0; np < 4; np++) {
            uint32_t bd = bBase + (uint32_t)(np * 16 * SROW * 2) + ko;
            ldsm_x4(b_hi[np], bd);
            ldsm_x4(b_lo[np], bd + LO);
        }
        #pragma unroll
        for (int mi = 0; mi < 2; mi++) {
            #pragma unroll
            for (int ni = 0; ni < 8; ni++) {
                const uint32_t* bh = &b_hi[ni >> 1][(ni & 1) * 2];
                const uint32_t* bl = &b_lo[ni >> 1][(ni & 1) * 2];
                mma16816(acc[mi][ni], a_hi[mi], bh);
                mma16816(acc[mi][ni], a_hi[mi], bl);
                mma16816(acc[mi][ni], a_lo[mi], bh);
            }
        }
    }

    // ---- epilogue: C -= acc (direct RMW from fragments) ----
    int cr = lane >> 2;
    int cc2 = (lane & 3) * 2;
    #pragma unroll
    for (int mi = 0; mi < 2; mi++) {
        #pragma unroll
        for (int ni = 0; ni < 8; ni++) {
            int cc = col0 + wn + ni * 8 + cc2;
            if (cc < N) {
                int r0 = row0 + wm + mi * 16 + cr;
                if (r0 < N) {
                    float2* p = reinterpret_cast<float2*>(&M[(size_t)r0 * N + cc]);
                    float2 v = *p;
                    v.x -= acc[mi][ni][0]; v.y -= acc[mi][ni][1];
                    *p = v;
                }
                int r1 = row0 + wm + mi * 16 + cr + 8;
                if (r1 < N) {
                    float2* p = reinterpret_cast<float2*>(&M[(size_t)r1 * N + cc]);
                    float2 v = *p;
                    v.x -= acc[mi][ni][2]; v.y -= acc[mi][ni][3];
                    *p = v;
                }
            }
        }
    }
}

// ---------------- epilogue ---------------------------------------------------

__global__ void k_logdet() {
    int mat = blockIdx.x;
    __shared__ float sm[256];
    float s = 0.0f;
    for (int d = threadIdx.x; d < 1023; d += 256)
        s += logf(fabsf(g_LU[(size_t)mat * N * N + (size_t)d * N + d]));
    sm[threadIdx.x] = s;
    __syncthreads();
    for (int st = 128; st > 0; st >>= 1) {
        if (threadIdx.x < st) sm[threadIdx.x] += sm[threadIdx.x + st];
        __syncthreads();
    }
    if (threadIdx.x == 0) g_ld[mat] = sm[0];
}

__global__ void k_out(float* __restrict__ out) {
    int b = threadIdx.x;
    if (b < BATCH) out[b] = g_y[b] + g_ld[b] - g_ld[32];
}

// ---------------- launch ------------------------------------------------------
extern "C" void kernel_launch(void* const* d_in, const int* in_sizes, int n_in,
                              void* d_out, int out_size) {
    const int*   x  = (const int*)d_in[0];
    const float* W  = (const float*)d_in[1];
    const float* Vc = (const float*)d_in[2];
    const float* Ec = (const float*)d_in[3];
    float* out = (float*)d_out;
    (void)in_sizes; (void)n_in; (void)out_size;

    cudaFuncSetAttribute(k_gemm_mma, cudaFuncAttributeMaxDynamicSharedMemorySize, SM_MMA_BYTES);

    k_vsoftmax<<<4, 256>>>(Vc);
    k_pr<<<BATCH, 1024>>>(x);
    k_ws<<<N, 256>>>(W);
    k_sink<<<dim3(8, N - 1), 128>>>(x, Ec);
    k_fin<<<dim3(N, BATCH), 256>>>();

    for (int s = 0; s < 16; s++) {
        int k = s * 64;
        k_panelLU<<<NMAT, 256>>>(k);
        int m2 = N - k - 64;
        if (m2 > 0) {
            int gtr = (m2 + 255) / 256;
            int gx  = (m2 + 127) / 128;
            k_trsm<<<dim3(gtr, NMAT, 2), 256>>>(k);
            k_conv<<<dim3(m2 / 64, NMAT, 2), 256>>>(k);
            k_gemm_mma<<<dim3(gx, gx, NMAT), 256, SM_MMA_BYTES>>>(k);
        }
    }

    k_logdet<<<NMAT, 256>>>();
    k_out<<<1, 32>>>(out);
}